// round 11
// baseline (speedup 1.0000x reference)
#include <cuda_runtime.h>
#include <cuda_bf16.h>
#include <cstdint>
#include <cstddef>

#define NN 50000
#define EE 800000
#define HID 128
#define EDIM 32
#define XSTR 68      // transposed-X stride for proj kernels
#define NB_SCAN 196  // ceil(NN/256)
#define DSTR 136     // D staging stride (floats), 16B-aligned rows, conflict-spread

// ---------------- scratch (static __device__ — allocation-free) ----------------
__device__ __align__(16) float g_x0[(size_t)NN * HID];
__device__ __align__(16) float g_x1[(size_t)NN * HID];
__device__ __align__(16) float g_mx[(size_t)NN * HID];
__device__ __align__(16) float g_me[(size_t)NN * HID];
__device__ __align__(16) float g_scores[NN];
__device__ int g_src[EE];
__device__ int g_dst[EE];
__device__ int g_csr_src[EE];
__device__ int g_cnt[NN];
__device__ int g_rowptr[NN];
__device__ int g_cur[NN];
__device__ int g_partial[256];
__device__ unsigned g_maxbits;
__device__ float g_sum;
// B fragments of We^T in per-thread mma layout: [ks(2)][nb(16)][lane(32)][2] u32
__device__ __align__(16) uint32_t g_bfh[2 * 16 * 32 * 2];
__device__ __align__(16) uint32_t g_bfl[2 * 16 * 32 * 2];

// ---------------- helpers ----------------
__device__ __forceinline__ void red_add_v4(float* addr, float4 v) {
    asm volatile("red.global.add.v4.f32 [%0], {%1,%2,%3,%4};"
                 :: "l"(addr), "f"(v.x), "f"(v.y), "f"(v.z), "f"(v.w)
                 : "memory");
}
__device__ __forceinline__ unsigned long long fma2(unsigned long long a,
                                                   unsigned long long b,
                                                   unsigned long long c) {
    unsigned long long d;
    asm("fma.rn.f32x2 %0, %1, %2, %3;" : "=l"(d) : "l"(a), "l"(b), "l"(c));
    return d;
}
__device__ __forceinline__ unsigned long long dup2(float s) {
    unsigned long long d;
    asm("mov.b64 %0, {%1, %1};" : "=l"(d) : "f"(s));
    return d;
}
__device__ __forceinline__ void unpack2(unsigned long long v, float& lo, float& hi) {
    asm("mov.b64 {%0, %1}, %2;" : "=f"(lo), "=f"(hi) : "l"(v));
}
__device__ __forceinline__ unsigned enc_ordered(float f) {
    unsigned b = __float_as_uint(f);
    return (b & 0x80000000u) ? ~b : (b | 0x80000000u);
}
__device__ __forceinline__ float dec_ordered(unsigned u) {
    unsigned b = (u & 0x80000000u) ? (u ^ 0x80000000u) : ~u;
    return __uint_as_float(b);
}
// pack two fp32 -> bf16x2 (x low half, y high half), plus residuals
__device__ __forceinline__ uint32_t pack_bf16_hi(float x, float y) {
    uint32_t h;
    asm("cvt.rn.bf16x2.f32 %0, %1, %2;" : "=r"(h) : "f"(y), "f"(x));
    return h;
}
__device__ __forceinline__ uint32_t pack_bf16_lo(float x, float y, uint32_t h) {
    const float rx = x - __uint_as_float(h << 16);
    const float ry = y - __uint_as_float(h & 0xffff0000u);
    uint32_t l;
    asm("cvt.rn.bf16x2.f32 %0, %1, %2;" : "=r"(l) : "f"(ry), "f"(rx));
    return l;
}
// mma.sync m16n8k16 row.col f32.bf16.bf16.f32, C==D accumulate
__device__ __forceinline__ void mma_bf16(float& d0, float& d1, float& d2, float& d3,
                                         uint32_t a0, uint32_t a1, uint32_t a2,
                                         uint32_t a3, uint32_t b0, uint32_t b1) {
    asm volatile(
        "mma.sync.aligned.m16n8k16.row.col.f32.bf16.bf16.f32 "
        "{%0,%1,%2,%3}, {%4,%5,%6,%7}, {%8,%9}, {%0,%1,%2,%3};"
        : "+f"(d0), "+f"(d1), "+f"(d2), "+f"(d3)
        : "r"(a0), "r"(a1), "r"(a2), "r"(a3), "r"(b0), "r"(b1));
}

// ---------------- edge index normalization + cnt zeroing ----------------
__global__ void convert_edges(const void* __restrict__ ei) {
    __shared__ int is64;
    if (threadIdx.x == 0) {
        const int* p = (const int*)ei;
        int z = 0;
        #pragma unroll
        for (int i = 0; i < 64; i++) z |= p[2 * i + 1];
        is64 = (z == 0);
    }
    __syncthreads();
    const int idx = blockIdx.x * blockDim.x + threadIdx.x;
    const int stride = gridDim.x * blockDim.x;
    for (int i = idx; i < NN; i += stride) g_cnt[i] = 0;
    if (is64) {
        const long long* p = (const long long*)ei;
        for (int e = idx; e < EE; e += stride) {
            g_src[e] = (int)p[e];
            g_dst[e] = (int)p[EE + e];
        }
    } else {
        const int* p = (const int*)ei;
        for (int e = idx; e < EE; e += stride) {
            g_src[e] = p[e];
            g_dst[e] = p[EE + e];
        }
    }
}

// ---------------- CSR build ----------------
__global__ void hist_kernel() {
    const int idx = blockIdx.x * blockDim.x + threadIdx.x;
    const int stride = gridDim.x * blockDim.x;
    for (int e = idx; e < EE; e += stride) atomicAdd(&g_cnt[g_dst[e]], 1);
}

__global__ void scan_reduce() {
    __shared__ int sh[256];
    const int t = threadIdx.x;
    const int i = blockIdx.x * 256 + t;
    sh[t] = (i < NN) ? g_cnt[i] : 0;
    __syncthreads();
    #pragma unroll
    for (int o = 128; o; o >>= 1) {
        if (t < o) sh[t] += sh[t + o];
        __syncthreads();
    }
    if (t == 0) g_partial[blockIdx.x] = sh[0];
}

__global__ void scan_partials() {
    __shared__ int sh[256];
    const int t = threadIdx.x;
    const int v = (t < NB_SCAN) ? g_partial[t] : 0;
    sh[t] = v;
    __syncthreads();
    #pragma unroll
    for (int off = 1; off < 256; off <<= 1) {
        int a = (t >= off) ? sh[t - off] : 0;
        __syncthreads();
        sh[t] += a;
        __syncthreads();
    }
    g_partial[t] = sh[t] - v;   // exclusive
}

__global__ void scan_final() {
    __shared__ int sh[256];
    const int t = threadIdx.x;
    const int i = blockIdx.x * 256 + t;
    const int v = (i < NN) ? g_cnt[i] : 0;
    sh[t] = v;
    __syncthreads();
    #pragma unroll
    for (int off = 1; off < 256; off <<= 1) {
        int a = (t >= off) ? sh[t - off] : 0;
        __syncthreads();
        sh[t] += a;
        __syncthreads();
    }
    if (i < NN) {
        const int excl = sh[t] - v + g_partial[blockIdx.x];
        g_rowptr[i] = excl;
        g_cur[i] = excl;
    }
}

__global__ void fill_kernel() {
    const int idx = blockIdx.x * blockDim.x + threadIdx.x;
    const int stride = gridDim.x * blockDim.x;
    for (int e = idx; e < EE; e += stride) {
        const int d = g_dst[e];
        const int p = atomicAdd(&g_cur[d], 1);
        g_csr_src[p] = g_src[e];
    }
}

// ---------------- zero m_e + scalars ----------------
__global__ void zero_me() {
    const int n4 = NN * HID / 4;
    float4* a = (float4*)g_me;
    const float4 z = make_float4(0.f, 0.f, 0.f, 0.f);
    for (int i = blockIdx.x * blockDim.x + threadIdx.x; i < n4;
         i += gridDim.x * blockDim.x)
        a[i] = z;
    if (blockIdx.x == 0 && threadIdx.x == 0) { g_maxbits = 0u; g_sum = 0.f; }
}

// ---------------- B-fragment precompute: We[32][128] -> mma per-thread layout ----
// B frag (m16n8k16, col): lane holds B[k0..k0+1][n] in b0, B[k0+8..k0+9][n] in b1,
// where n = nb*8 + lane/4, k0 = ks*16 + (lane%4)*2.
__global__ void wconv_kernel(const float* __restrict__ We) {
    const int t = blockIdx.x * blockDim.x + threadIdx.x;
    if (t >= 1024) return;
    const int lane = t & 31;
    const int nb = (t >> 5) & 15;
    const int ks = t >> 9;
    const int n = nb * 8 + (lane >> 2);
    const int k0 = ks * 16 + (lane & 3) * 2;
    const float w00 = We[(k0 + 0) * 128 + n];
    const float w01 = We[(k0 + 1) * 128 + n];
    const float w10 = We[(k0 + 8) * 128 + n];
    const float w11 = We[(k0 + 9) * 128 + n];
    const uint32_t b0h = pack_bf16_hi(w00, w01);
    const uint32_t b1h = pack_bf16_hi(w10, w11);
    const uint32_t b0l = pack_bf16_lo(w00, w01, b0h);
    const uint32_t b1l = pack_bf16_lo(w10, w11, b1h);
    const int idx = ((ks * 16 + nb) * 32 + lane) * 2;
    g_bfh[idx] = b0h; g_bfh[idx + 1] = b1h;
    g_bfl[idx] = b0l; g_bfl[idx + 1] = b1l;
}

// ---------------- mma.sync edge projection + segment-sum into m_e ----------------
// Block = 256 threads = 8 warps, 128 edges/block. Warp w owns rows [w*16,+16).
// D = Ah*Bh + Ah*Bl + Al*Bh (bf16x3 ~ fp32), bias folded into acc init.
// D staged in smem, epilogue relu + red.add.v4 (same atomic pattern as R8).
__global__ __launch_bounds__(256)
void edge_proj_mma(const float* __restrict__ EF,
                   const float* __restrict__ be) {
    extern __shared__ float dsm[];                 // [128][DSTR] + dst[128]
    int* dst_s = (int*)(dsm + 128 * DSTR);
    const int tid = threadIdx.x;
    const int lane = tid & 31;
    const int w = tid >> 5;
    const int tile0 = blockIdx.x * 128;

    if (tid < 128) dst_s[tid] = g_dst[tile0 + tid];

    // ---- A fragments straight from global (no smem, no ldmatrix) ----
    const int g = lane >> 2;
    const int c0 = (lane & 3) * 2;
    const float* rowp0 = EF + (size_t)(tile0 + w * 16 + g) * EDIM;
    const float* rowp1 = rowp0 + 8 * EDIM;
    uint32_t ah[2][4], al[2][4];
    #pragma unroll
    for (int ks = 0; ks < 2; ks++) {
        #pragma unroll
        for (int half = 0; half < 2; half++) {
            const int k = ks * 16 + half * 8 + c0;
            const float2 f0 = *(const float2*)(rowp0 + k);
            const float2 f1 = *(const float2*)(rowp1 + k);
            const uint32_t h0 = pack_bf16_hi(f0.x, f0.y);
            const uint32_t h1 = pack_bf16_hi(f1.x, f1.y);
            ah[ks][half * 2 + 0] = h0;
            ah[ks][half * 2 + 1] = h1;
            al[ks][half * 2 + 0] = pack_bf16_lo(f0.x, f0.y, h0);
            al[ks][half * 2 + 1] = pack_bf16_lo(f1.x, f1.y, h1);
        }
    }

    // ---- 16 n-blocks of m16n8, 2 k-steps, 3 mma each ----
    const uint32_t* bh = g_bfh;
    const uint32_t* bl = g_bfl;
    #pragma unroll
    for (int nb = 0; nb < 16; nb++) {
        const float2 bb = *(const float2*)(be + nb * 8 + c0);
        float d0 = bb.x, d1 = bb.y, d2 = bb.x, d3 = bb.y;
        #pragma unroll
        for (int ks = 0; ks < 2; ks++) {
            const int bi = ((ks * 16 + nb) * 32 + lane) * 2;
            const uint32_t bh0 = bh[bi], bh1 = bh[bi + 1];
            const uint32_t bl0 = bl[bi], bl1 = bl[bi + 1];
            mma_bf16(d0, d1, d2, d3,
                     ah[ks][0], ah[ks][1], ah[ks][2], ah[ks][3], bh0, bh1);
            mma_bf16(d0, d1, d2, d3,
                     ah[ks][0], ah[ks][1], ah[ks][2], ah[ks][3], bl0, bl1);
            mma_bf16(d0, d1, d2, d3,
                     al[ks][0], al[ks][1], al[ks][2], al[ks][3], bh0, bh1);
        }
        float* dp = dsm + (size_t)(w * 16 + g) * DSTR + nb * 8 + c0;
        *(float2*)dp = make_float2(d0, d1);
        *(float2*)(dp + 8 * DSTR) = make_float2(d2, d3);
    }
    __syncthreads();

    // ---- epilogue: relu + red.add.v4 into g_me[dst] ----
    const int row = w * 16 + (lane >> 1);
    const int half = lane & 1;
    const int dst = dst_s[row];
    float* outp = g_me + (size_t)dst * 128 + half * 64;
    const float* drow = dsm + (size_t)row * DSTR + half * 64;
    #pragma unroll
    for (int j = 0; j < 16; j++) {
        float4 v = *(const float4*)(drow + j * 4);
        v.x = fmaxf(v.x, 0.f); v.y = fmaxf(v.y, 0.f);
        v.z = fmaxf(v.z, 0.f); v.w = fmaxf(v.w, 0.f);
        red_add_v4(outp + j * 4, v);
    }
}

// ---------------- f32x2 row-projection GEMM (R8 geometry, unchanged) -----------
template <int K, bool CONCAT>
__global__ void proj_kernel(const float* __restrict__ in0,
                            const float* __restrict__ in1,
                            const float* __restrict__ W,
                            const float* __restrict__ bias,
                            float* __restrict__ out, int rows) {
    extern __shared__ float sh[];
    float* W_s = sh;             // K*128 floats
    float* X_s = sh + K * 128;   // K*XSTR floats (transposed, padded)
    const int tid = threadIdx.x;

    {
        const float4* Wg = (const float4*)W;
        float4* Ws4 = (float4*)W_s;
        const int n4 = K * 128 / 4;
        for (int i = tid; i < n4; i += 256) Ws4[i] = Wg[i];
    }
    const int tile0 = blockIdx.x * 64;
    {
        const int KC = K / 4;
        for (int i = tid; i < 64 * KC; i += 256) {
            const int r = i & 63, kc = i >> 6;
            const int g = tile0 + r;
            float4 v = make_float4(0.f, 0.f, 0.f, 0.f);
            if (g < rows) {
                if (CONCAT) {
                    v = (kc < 32) ? ((const float4*)(in0 + (size_t)g * 128))[kc]
                                  : ((const float4*)(in1 + (size_t)g * 128))[kc - 32];
                } else {
                    v = ((const float4*)(in0 + (size_t)g * K))[kc];
                }
            }
            float* xp = &X_s[(kc * 4) * XSTR + r];
            xp[0 * XSTR] = v.x;
            xp[1 * XSTR] = v.y;
            xp[2 * XSTR] = v.z;
            xp[3 * XSTR] = v.w;
        }
    }
    __syncthreads();

    const int lane = tid & 31;
    const int w = tid >> 5;
    const int rb = w * 8;
    const float4 bias4 = ((const float4*)bias)[lane];
    unsigned long long acc[4][4];
    {
        const unsigned long long b0 = dup2(bias4.x), b1 = dup2(bias4.y);
        const unsigned long long b2 = dup2(bias4.z), b3 = dup2(bias4.w);
        #pragma unroll
        for (int p = 0; p < 4; p++) {
            acc[p][0] = b0; acc[p][1] = b1; acc[p][2] = b2; acc[p][3] = b3;
        }
    }

    #pragma unroll 4
    for (int k = 0; k < K; k++) {
        const float4 wv = ((const float4*)&W_s[k * 128])[lane];
        const unsigned long long w0 = dup2(wv.x), w1 = dup2(wv.y);
        const unsigned long long w2 = dup2(wv.z), w3 = dup2(wv.w);
        const float* xb = &X_s[k * XSTR + rb];
        const ulonglong2 xlo = *(const ulonglong2*)(xb + 0);
        const ulonglong2 xhi = *(const ulonglong2*)(xb + 4);
        const unsigned long long xp[4] = {xlo.x, xlo.y, xhi.x, xhi.y};
        #pragma unroll
        for (int p = 0; p < 4; p++) {
            acc[p][0] = fma2(xp[p], w0, acc[p][0]);
            acc[p][1] = fma2(xp[p], w1, acc[p][1]);
            acc[p][2] = fma2(xp[p], w2, acc[p][2]);
            acc[p][3] = fma2(xp[p], w3, acc[p][3]);
        }
    }

    #pragma unroll
    for (int p = 0; p < 4; p++) {
        float4 v0, v1;
        unpack2(acc[p][0], v0.x, v1.x);
        unpack2(acc[p][1], v0.y, v1.y);
        unpack2(acc[p][2], v0.z, v1.z);
        unpack2(acc[p][3], v0.w, v1.w);
        const int g0 = tile0 + rb + 2 * p;
        if (g0 < rows) {
            v0.x = fmaxf(v0.x, 0.f); v0.y = fmaxf(v0.y, 0.f);
            v0.z = fmaxf(v0.z, 0.f); v0.w = fmaxf(v0.w, 0.f);
            ((float4*)(out + (size_t)g0 * 128))[lane] = v0;
        }
        if (g0 + 1 < rows) {
            v1.x = fmaxf(v1.x, 0.f); v1.y = fmaxf(v1.y, 0.f);
            v1.z = fmaxf(v1.z, 0.f); v1.w = fmaxf(v1.w, 0.f);
            ((float4*)(out + (size_t)(g0 + 1) * 128))[lane] = v1;
        }
    }
}

// ---------------- CSR aggregation (R8, unchanged) ----------------
__global__ void gather_csr(const float* __restrict__ x) {
    const int lane = threadIdx.x & 31;
    const int warp = (blockIdx.x * blockDim.x + threadIdx.x) >> 5;
    const int nwarps = (gridDim.x * blockDim.x) >> 5;
    for (int n = warp; n < NN; n += nwarps) {
        const int start = g_rowptr[n];
        const int deg = g_cnt[n];
        float4 a0 = make_float4(0.f, 0.f, 0.f, 0.f);
        float4 a1 = make_float4(0.f, 0.f, 0.f, 0.f);
        for (int j0 = 0; j0 < deg; j0 += 32) {
            const int m = min(32, deg - j0);
            const int idx = (lane < m) ? g_csr_src[start + j0 + lane] : 0;
            int j = 0;
            for (; j + 1 < m; j += 2) {
                const int s0 = __shfl_sync(0xffffffffu, idx, j);
                const int s1 = __shfl_sync(0xffffffffu, idx, j + 1);
                const float4 v0 = ((const float4*)(x + (size_t)s0 * 128))[lane];
                const float4 v1 = ((const float4*)(x + (size_t)s1 * 128))[lane];
                a0.x += v0.x; a0.y += v0.y; a0.z += v0.z; a0.w += v0.w;
                a1.x += v1.x; a1.y += v1.y; a1.z += v1.z; a1.w += v1.w;
            }
            if (j < m) {
                const int s0 = __shfl_sync(0xffffffffu, idx, j);
                const float4 v0 = ((const float4*)(x + (size_t)s0 * 128))[lane];
                a0.x += v0.x; a0.y += v0.y; a0.z += v0.z; a0.w += v0.w;
            }
        }
        a0.x += a1.x; a0.y += a1.y; a0.z += a1.z; a0.w += a1.w;
        ((float4*)(g_mx + (size_t)n * 128))[lane] = a0;
    }
}

// ---------------- scores + global max ----------------
__global__ void scores_kernel(const float* __restrict__ x,
                              const float* __restrict__ Wo,
                              const float* __restrict__ bo) {
    const int lane = threadIdx.x & 31;
    const int w = threadIdx.x >> 5;
    const int nw = blockDim.x >> 5;
    const float4 wv = ((const float4*)Wo)[lane];
    const float b = *bo;
    float lmax = -3.402823466e38f;
    for (int n = blockIdx.x * nw + w; n < NN; n += gridDim.x * nw) {
        const float4 xv = ((const float4*)(x + (size_t)n * 128))[lane];
        float d = xv.x * wv.x + xv.y * wv.y + xv.z * wv.z + xv.w * wv.w;
        #pragma unroll
        for (int o = 16; o; o >>= 1) d += __shfl_down_sync(0xffffffffu, d, o);
        if (lane == 0) {
            const float sc = d + b;
            g_scores[n] = sc;
            if (sc > lmax) lmax = sc;
        }
    }
    __shared__ float sm[8];
    lmax = __shfl_sync(0xffffffffu, lmax, 0);
    if (lane == 0) sm[w] = lmax;
    __syncthreads();
    if (threadIdx.x == 0) {
        float m = sm[0];
        for (int i = 1; i < nw; i++) m = fmaxf(m, sm[i]);
        atomicMax(&g_maxbits, enc_ordered(m));
    }
}

// ---------------- sum of exp ----------------
__global__ void sum_kernel() {
    const float maxf = dec_ordered(g_maxbits);
    float s = 0.f;
    for (int n = blockIdx.x * blockDim.x + threadIdx.x; n < NN;
         n += gridDim.x * blockDim.x)
        s += expf(g_scores[n] - maxf);
    #pragma unroll
    for (int o = 16; o; o >>= 1) s += __shfl_down_sync(0xffffffffu, s, o);
    __shared__ float sm[8];
    const int lane = threadIdx.x & 31, w = threadIdx.x >> 5;
    if (lane == 0) sm[w] = s;
    __syncthreads();
    if (threadIdx.x == 0) {
        float t = 0.f;
        const int nw = blockDim.x >> 5;
        for (int i = 0; i < nw; i++) t += sm[i];
        atomicAdd(&g_sum, t);
    }
}

// ---------------- normalize ----------------
__global__ void finalize_kernel(float* __restrict__ out) {
    const float maxf = dec_ordered(g_maxbits);
    const float inv = 1.0f / g_sum;
    const int n = blockIdx.x * blockDim.x + threadIdx.x;
    if (n < NN) out[n] = expf(g_scores[n] - maxf) * inv;
}

// ---------------- launch ----------------
extern "C" void kernel_launch(void* const* d_in, const int* in_sizes, int n_in,
                              void* d_out, int out_size) {
    const float* NF = (const float*)d_in[0];
    const float* EF = (const float*)d_in[1];
    const float* Wn = (const float*)d_in[2];
    const float* bn = (const float*)d_in[3];
    const float* We = (const float*)d_in[4];
    const float* be = (const float*)d_in[5];
    const float* W1 = (const float*)d_in[6];
    const float* b1 = (const float*)d_in[7];
    const float* W2 = (const float*)d_in[8];
    const float* b2 = (const float*)d_in[9];
    const float* Wo = (const float*)d_in[10];
    const float* bo = (const float*)d_in[11];
    const void*  EI = d_in[12];
    float* out = (float*)d_out;

    float *px0, *px1, *pmx, *pme;
    cudaGetSymbolAddress((void**)&px0, g_x0);
    cudaGetSymbolAddress((void**)&px1, g_x1);
    cudaGetSymbolAddress((void**)&pmx, g_mx);
    cudaGetSymbolAddress((void**)&pme, g_me);

    const int SMEM_128 = (128 * 128 + 128 * XSTR) * 4;   // ~99 KB
    const int SMEM_256 = (256 * 128 + 256 * XSTR) * 4;   // ~198 KB
    const int SMEM_EP  = (128 * DSTR) * 4 + 128 * 4;     // ~70 KB
    cudaFuncSetAttribute(proj_kernel<128, false>,
                         cudaFuncAttributeMaxDynamicSharedMemorySize, SMEM_128);
    cudaFuncSetAttribute(proj_kernel<256, true>,
                         cudaFuncAttributeMaxDynamicSharedMemorySize, SMEM_256);
    cudaFuncSetAttribute(edge_proj_mma,
                         cudaFuncAttributeMaxDynamicSharedMemorySize, SMEM_EP);

    const int nTilesN = (NN + 63) / 64;   // 782
    const int nTilesE = EE / 128;         // 6250

    // edge index normalization + cnt zeroing
    convert_edges<<<512, 256>>>(EI);
    // zero m_e + softmax scalars; precompute We B-fragments (bf16 hi/lo)
    zero_me<<<2048, 256>>>();
    wconv_kernel<<<4, 256>>>(We);
    // CSR build (topology computed once, reused by both conv layers)
    hist_kernel<<<512, 256>>>();
    scan_reduce<<<NB_SCAN, 256>>>();
    scan_partials<<<1, 256>>>();
    scan_final<<<NB_SCAN, 256>>>();
    fill_kernel<<<512, 256>>>();
    // x0 = relu(NF @ Wn + bn)
    proj_kernel<128, false><<<nTilesN, 256, SMEM_128>>>(NF, nullptr, Wn, bn, px0, NN);
    // m_e = segment_sum(relu(EF @ We + be), dst)  — mma.sync bf16x3
    edge_proj_mma<<<nTilesE, 256, SMEM_EP>>>(EF, be);
    // layer 1
    gather_csr<<<1184, 256>>>(px0);
    proj_kernel<256, true><<<nTilesN, 256, SMEM_256>>>(pmx, pme, W1, b1, px1, NN);
    // layer 2
    gather_csr<<<1184, 256>>>(px1);
    proj_kernel<256, true><<<nTilesN, 256, SMEM_256>>>(pmx, pme, W2, b2, px0, NN);
    // scores + softmax
    scores_kernel<<<512, 128>>>(px0, Wo, bo);
    sum_kernel<<<512, 256>>>();
    finalize_kernel<<<(NN + 255) / 256, 256>>>(out);
}

// round 12
// speedup vs baseline: 1.1321x; 1.1321x over previous
#include <cuda_runtime.h>
#include <cuda_bf16.h>
#include <cstdint>
#include <cstddef>

#define NN 50000
#define EE 800000
#define HID 128
#define EDIM 32
#define XSTR 68      // transposed-X stride for proj kernels
#define NB_SCAN 196  // ceil(NN/256)

// ---------------- scratch (static __device__ — allocation-free) ----------------
__device__ __align__(16) float g_x0[(size_t)NN * HID];
__device__ __align__(16) float g_x1[(size_t)NN * HID];
__device__ __align__(16) float g_mx[(size_t)NN * HID];
__device__ __align__(16) float g_me[(size_t)NN * HID];
__device__ __align__(16) float g_scores[NN];
__device__ int g_src[EE];
__device__ int g_dst[EE];
__device__ int g_csr_src[EE];
__device__ int g_cnt[NN];
__device__ int g_rowptr[NN];
__device__ int g_cur[NN];
__device__ int g_partial[256];
__device__ unsigned g_maxbits;
__device__ float g_sum;
// B fragments of We^T in per-thread mma layout: [ks(2)][nb(16)][lane(32)][2] u32
__device__ __align__(16) uint32_t g_bfh[2 * 16 * 32 * 2];
__device__ __align__(16) uint32_t g_bfl[2 * 16 * 32 * 2];

// ---------------- helpers ----------------
__device__ __forceinline__ void red_add_v4(float* addr, float4 v) {
    asm volatile("red.global.add.v4.f32 [%0], {%1,%2,%3,%4};"
                 :: "l"(addr), "f"(v.x), "f"(v.y), "f"(v.z), "f"(v.w)
                 : "memory");
}
__device__ __forceinline__ unsigned long long fma2(unsigned long long a,
                                                   unsigned long long b,
                                                   unsigned long long c) {
    unsigned long long d;
    asm("fma.rn.f32x2 %0, %1, %2, %3;" : "=l"(d) : "l"(a), "l"(b), "l"(c));
    return d;
}
__device__ __forceinline__ unsigned long long dup2(float s) {
    unsigned long long d;
    asm("mov.b64 %0, {%1, %1};" : "=l"(d) : "f"(s));
    return d;
}
__device__ __forceinline__ void unpack2(unsigned long long v, float& lo, float& hi) {
    asm("mov.b64 {%0, %1}, %2;" : "=f"(lo), "=f"(hi) : "l"(v));
}
__device__ __forceinline__ unsigned enc_ordered(float f) {
    unsigned b = __float_as_uint(f);
    return (b & 0x80000000u) ? ~b : (b | 0x80000000u);
}
__device__ __forceinline__ float dec_ordered(unsigned u) {
    unsigned b = (u & 0x80000000u) ? (u ^ 0x80000000u) : ~u;
    return __uint_as_float(b);
}
// pack two fp32 -> bf16x2 (x low half, y high half), plus residuals
__device__ __forceinline__ uint32_t pack_bf16_hi(float x, float y) {
    uint32_t h;
    asm("cvt.rn.bf16x2.f32 %0, %1, %2;" : "=r"(h) : "f"(y), "f"(x));
    return h;
}
__device__ __forceinline__ uint32_t pack_bf16_lo(float x, float y, uint32_t h) {
    const float rx = x - __uint_as_float(h << 16);
    const float ry = y - __uint_as_float(h & 0xffff0000u);
    uint32_t l;
    asm("cvt.rn.bf16x2.f32 %0, %1, %2;" : "=r"(l) : "f"(ry), "f"(rx));
    return l;
}
// mma.sync m16n8k16 row.col f32.bf16.bf16.f32, C==D accumulate
__device__ __forceinline__ void mma_bf16(float& d0, float& d1, float& d2, float& d3,
                                         uint32_t a0, uint32_t a1, uint32_t a2,
                                         uint32_t a3, uint32_t b0, uint32_t b1) {
    asm volatile(
        "mma.sync.aligned.m16n8k16.row.col.f32.bf16.bf16.f32 "
        "{%0,%1,%2,%3}, {%4,%5,%6,%7}, {%8,%9}, {%0,%1,%2,%3};"
        : "+f"(d0), "+f"(d1), "+f"(d2), "+f"(d3)
        : "r"(a0), "r"(a1), "r"(a2), "r"(a3), "r"(b0), "r"(b1));
}

// ---------------- edge index normalization + cnt zeroing ----------------
__global__ void convert_edges(const void* __restrict__ ei) {
    __shared__ int is64;
    if (threadIdx.x == 0) {
        const int* p = (const int*)ei;
        int z = 0;
        #pragma unroll
        for (int i = 0; i < 64; i++) z |= p[2 * i + 1];
        is64 = (z == 0);
    }
    __syncthreads();
    const int idx = blockIdx.x * blockDim.x + threadIdx.x;
    const int stride = gridDim.x * blockDim.x;
    for (int i = idx; i < NN; i += stride) g_cnt[i] = 0;
    if (is64) {
        const long long* p = (const long long*)ei;
        for (int e = idx; e < EE; e += stride) {
            g_src[e] = (int)p[e];
            g_dst[e] = (int)p[EE + e];
        }
    } else {
        const int* p = (const int*)ei;
        for (int e = idx; e < EE; e += stride) {
            g_src[e] = p[e];
            g_dst[e] = p[EE + e];
        }
    }
}

// ---------------- CSR build ----------------
__global__ void hist_kernel() {
    const int idx = blockIdx.x * blockDim.x + threadIdx.x;
    const int stride = gridDim.x * blockDim.x;
    for (int e = idx; e < EE; e += stride) atomicAdd(&g_cnt[g_dst[e]], 1);
}

__global__ void scan_reduce() {
    __shared__ int sh[256];
    const int t = threadIdx.x;
    const int i = blockIdx.x * 256 + t;
    sh[t] = (i < NN) ? g_cnt[i] : 0;
    __syncthreads();
    #pragma unroll
    for (int o = 128; o; o >>= 1) {
        if (t < o) sh[t] += sh[t + o];
        __syncthreads();
    }
    if (t == 0) g_partial[blockIdx.x] = sh[0];
}

__global__ void scan_partials() {
    __shared__ int sh[256];
    const int t = threadIdx.x;
    const int v = (t < NB_SCAN) ? g_partial[t] : 0;
    sh[t] = v;
    __syncthreads();
    #pragma unroll
    for (int off = 1; off < 256; off <<= 1) {
        int a = (t >= off) ? sh[t - off] : 0;
        __syncthreads();
        sh[t] += a;
        __syncthreads();
    }
    g_partial[t] = sh[t] - v;   // exclusive
}

__global__ void scan_final() {
    __shared__ int sh[256];
    const int t = threadIdx.x;
    const int i = blockIdx.x * 256 + t;
    const int v = (i < NN) ? g_cnt[i] : 0;
    sh[t] = v;
    __syncthreads();
    #pragma unroll
    for (int off = 1; off < 256; off <<= 1) {
        int a = (t >= off) ? sh[t - off] : 0;
        __syncthreads();
        sh[t] += a;
        __syncthreads();
    }
    if (i < NN) {
        const int excl = sh[t] - v + g_partial[blockIdx.x];
        g_rowptr[i] = excl;
        g_cur[i] = excl;
    }
}

__global__ void fill_kernel() {
    const int idx = blockIdx.x * blockDim.x + threadIdx.x;
    const int stride = gridDim.x * blockDim.x;
    for (int e = idx; e < EE; e += stride) {
        const int d = g_dst[e];
        const int p = atomicAdd(&g_cur[d], 1);
        g_csr_src[p] = g_src[e];
    }
}

// ---------------- zero m_e + scalars ----------------
__global__ void zero_me() {
    const int n4 = NN * HID / 4;
    float4* a = (float4*)g_me;
    const float4 z = make_float4(0.f, 0.f, 0.f, 0.f);
    for (int i = blockIdx.x * blockDim.x + threadIdx.x; i < n4;
         i += gridDim.x * blockDim.x)
        a[i] = z;
    if (blockIdx.x == 0 && threadIdx.x == 0) { g_maxbits = 0u; g_sum = 0.f; }
}

// ---------------- B-fragment precompute: We[32][128] -> mma per-thread layout ----
// B frag (m16n8k16, col): lane holds B[k0..k0+1][n] in b0, B[k0+8..k0+9][n] in b1,
// where n = nb*8 + lane/4, k0 = ks*16 + (lane%4)*2.
__global__ void wconv_kernel(const float* __restrict__ We) {
    const int t = blockIdx.x * blockDim.x + threadIdx.x;
    if (t >= 1024) return;
    const int lane = t & 31;
    const int nb = (t >> 5) & 15;
    const int ks = t >> 9;
    const int n = nb * 8 + (lane >> 2);
    const int k0 = ks * 16 + (lane & 3) * 2;
    const float w00 = We[(k0 + 0) * 128 + n];
    const float w01 = We[(k0 + 1) * 128 + n];
    const float w10 = We[(k0 + 8) * 128 + n];
    const float w11 = We[(k0 + 9) * 128 + n];
    const uint32_t b0h = pack_bf16_hi(w00, w01);
    const uint32_t b1h = pack_bf16_hi(w10, w11);
    const uint32_t b0l = pack_bf16_lo(w00, w01, b0h);
    const uint32_t b1l = pack_bf16_lo(w10, w11, b1h);
    const int idx = ((ks * 16 + nb) * 32 + lane) * 2;
    g_bfh[idx] = b0h; g_bfh[idx + 1] = b1h;
    g_bfl[idx] = b0l; g_bfl[idx + 1] = b1l;
}

// ---------------- mma.sync edge projection + segment-sum into m_e ----------------
// Block = 256 threads = 8 warps, 128 edges/block. Warp w owns rows [w*16,+16).
// D = Ah*Bh + Ah*Bl + Al*Bh (bf16x3 ~ fp32), bias folded into acc init.
// NO smem: D fragments assembled into float4 via shfl_xor(1) and red.add.v4'd
// directly into g_me inside the nb loop (atomics overlap MMA).
// Fragment map: d0,d1 = row g cols c0,c0+1; d2,d3 = row g+8 same cols,
// g = lane>>2, c0 = (lane&3)*2. Pair lanes (lane^1) cover cols base..base+3,
// base = (lane&2)*2: even lane emits row g, odd lane emits row g+8.
__global__ __launch_bounds__(256)
void edge_proj_mma(const float* __restrict__ EF,
                   const float* __restrict__ be) {
    const int tid = threadIdx.x;
    const int lane = tid & 31;
    const int w = tid >> 5;
    const int tile0 = blockIdx.x * 128;

    const int g = lane >> 2;
    const int c0 = (lane & 3) * 2;

    // this thread's atomic target row: even lane -> row g, odd lane -> row g+8
    const int myrow = w * 16 + g + ((lane & 1) ? 8 : 0);
    const int dst = __ldg(&g_dst[tile0 + myrow]);
    float* outp = g_me + (size_t)dst * 128 + (lane & 2) * 2;

    // ---- A fragments straight from global (no smem, no ldmatrix) ----
    const float* rowp0 = EF + (size_t)(tile0 + w * 16 + g) * EDIM;
    const float* rowp1 = rowp0 + 8 * EDIM;
    uint32_t ah[2][4], al[2][4];
    #pragma unroll
    for (int ks = 0; ks < 2; ks++) {
        #pragma unroll
        for (int half = 0; half < 2; half++) {
            const int k = ks * 16 + half * 8 + c0;
            const float2 f0 = *(const float2*)(rowp0 + k);
            const float2 f1 = *(const float2*)(rowp1 + k);
            const uint32_t h0 = pack_bf16_hi(f0.x, f0.y);
            const uint32_t h1 = pack_bf16_hi(f1.x, f1.y);
            ah[ks][half * 2 + 0] = h0;
            ah[ks][half * 2 + 1] = h1;
            al[ks][half * 2 + 0] = pack_bf16_lo(f0.x, f0.y, h0);
            al[ks][half * 2 + 1] = pack_bf16_lo(f1.x, f1.y, h1);
        }
    }

    // ---- 16 n-blocks of m16n8, 2 k-steps, 3 mma each; flush via shfl + red.v4 ----
    const uint32_t* bh = g_bfh;
    const uint32_t* bl = g_bfl;
    #pragma unroll
    for (int nb = 0; nb < 16; nb++) {
        const float2 bb = *(const float2*)(be + nb * 8 + c0);
        float d0 = bb.x, d1 = bb.y, d2 = bb.x, d3 = bb.y;
        #pragma unroll
        for (int ks = 0; ks < 2; ks++) {
            const int bi = ((ks * 16 + nb) * 32 + lane) * 2;
            const uint32_t bh0 = bh[bi], bh1 = bh[bi + 1];
            const uint32_t bl0 = bl[bi], bl1 = bl[bi + 1];
            mma_bf16(d0, d1, d2, d3,
                     ah[ks][0], ah[ks][1], ah[ks][2], ah[ks][3], bh0, bh1);
            mma_bf16(d0, d1, d2, d3,
                     ah[ks][0], ah[ks][1], ah[ks][2], ah[ks][3], bl0, bl1);
            mma_bf16(d0, d1, d2, d3,
                     al[ks][0], al[ks][1], al[ks][2], al[ks][3], bh0, bh1);
        }
        // assemble float4 with neighbor lane (lane^1)
        const float p0 = __shfl_xor_sync(0xffffffffu, d0, 1);
        const float p1 = __shfl_xor_sync(0xffffffffu, d1, 1);
        const float p2 = __shfl_xor_sync(0xffffffffu, d2, 1);
        const float p3 = __shfl_xor_sync(0xffffffffu, d3, 1);
        float4 v;
        if ((lane & 1) == 0) {
            v = make_float4(d0, d1, p0, p1);   // row g, cols base..base+3
        } else {
            v = make_float4(p2, p3, d2, d3);   // row g+8, cols base..base+3
        }
        v.x = fmaxf(v.x, 0.f); v.y = fmaxf(v.y, 0.f);
        v.z = fmaxf(v.z, 0.f); v.w = fmaxf(v.w, 0.f);
        red_add_v4(outp + nb * 8, v);
    }
}

// ---------------- f32x2 row-projection GEMM (R8 geometry, unchanged) -----------
template <int K, bool CONCAT>
__global__ void proj_kernel(const float* __restrict__ in0,
                            const float* __restrict__ in1,
                            const float* __restrict__ W,
                            const float* __restrict__ bias,
                            float* __restrict__ out, int rows) {
    extern __shared__ float sh[];
    float* W_s = sh;             // K*128 floats
    float* X_s = sh + K * 128;   // K*XSTR floats (transposed, padded)
    const int tid = threadIdx.x;

    {
        const float4* Wg = (const float4*)W;
        float4* Ws4 = (float4*)W_s;
        const int n4 = K * 128 / 4;
        for (int i = tid; i < n4; i += 256) Ws4[i] = Wg[i];
    }
    const int tile0 = blockIdx.x * 64;
    {
        const int KC = K / 4;
        for (int i = tid; i < 64 * KC; i += 256) {
            const int r = i & 63, kc = i >> 6;
            const int g = tile0 + r;
            float4 v = make_float4(0.f, 0.f, 0.f, 0.f);
            if (g < rows) {
                if (CONCAT) {
                    v = (kc < 32) ? ((const float4*)(in0 + (size_t)g * 128))[kc]
                                  : ((const float4*)(in1 + (size_t)g * 128))[kc - 32];
                } else {
                    v = ((const float4*)(in0 + (size_t)g * K))[kc];
                }
            }
            float* xp = &X_s[(kc * 4) * XSTR + r];
            xp[0 * XSTR] = v.x;
            xp[1 * XSTR] = v.y;
            xp[2 * XSTR] = v.z;
            xp[3 * XSTR] = v.w;
        }
    }
    __syncthreads();

    const int lane = tid & 31;
    const int w = tid >> 5;
    const int rb = w * 8;
    const float4 bias4 = ((const float4*)bias)[lane];
    unsigned long long acc[4][4];
    {
        const unsigned long long b0 = dup2(bias4.x), b1 = dup2(bias4.y);
        const unsigned long long b2 = dup2(bias4.z), b3 = dup2(bias4.w);
        #pragma unroll
        for (int p = 0; p < 4; p++) {
            acc[p][0] = b0; acc[p][1] = b1; acc[p][2] = b2; acc[p][3] = b3;
        }
    }

    #pragma unroll 4
    for (int k = 0; k < K; k++) {
        const float4 wv = ((const float4*)&W_s[k * 128])[lane];
        const unsigned long long w0 = dup2(wv.x), w1 = dup2(wv.y);
        const unsigned long long w2 = dup2(wv.z), w3 = dup2(wv.w);
        const float* xb = &X_s[k * XSTR + rb];
        const ulonglong2 xlo = *(const ulonglong2*)(xb + 0);
        const ulonglong2 xhi = *(const ulonglong2*)(xb + 4);
        const unsigned long long xp[4] = {xlo.x, xlo.y, xhi.x, xhi.y};
        #pragma unroll
        for (int p = 0; p < 4; p++) {
            acc[p][0] = fma2(xp[p], w0, acc[p][0]);
            acc[p][1] = fma2(xp[p], w1, acc[p][1]);
            acc[p][2] = fma2(xp[p], w2, acc[p][2]);
            acc[p][3] = fma2(xp[p], w3, acc[p][3]);
        }
    }

    #pragma unroll
    for (int p = 0; p < 4; p++) {
        float4 v0, v1;
        unpack2(acc[p][0], v0.x, v1.x);
        unpack2(acc[p][1], v0.y, v1.y);
        unpack2(acc[p][2], v0.z, v1.z);
        unpack2(acc[p][3], v0.w, v1.w);
        const int g0 = tile0 + rb + 2 * p;
        if (g0 < rows) {
            v0.x = fmaxf(v0.x, 0.f); v0.y = fmaxf(v0.y, 0.f);
            v0.z = fmaxf(v0.z, 0.f); v0.w = fmaxf(v0.w, 0.f);
            ((float4*)(out + (size_t)g0 * 128))[lane] = v0;
        }
        if (g0 + 1 < rows) {
            v1.x = fmaxf(v1.x, 0.f); v1.y = fmaxf(v1.y, 0.f);
            v1.z = fmaxf(v1.z, 0.f); v1.w = fmaxf(v1.w, 0.f);
            ((float4*)(out + (size_t)(g0 + 1) * 128))[lane] = v1;
        }
    }
}

// ---------------- CSR aggregation (R8, unchanged) ----------------
__global__ void gather_csr(const float* __restrict__ x) {
    const int lane = threadIdx.x & 31;
    const int warp = (blockIdx.x * blockDim.x + threadIdx.x) >> 5;
    const int nwarps = (gridDim.x * blockDim.x) >> 5;
    for (int n = warp; n < NN; n += nwarps) {
        const int start = g_rowptr[n];
        const int deg = g_cnt[n];
        float4 a0 = make_float4(0.f, 0.f, 0.f, 0.f);
        float4 a1 = make_float4(0.f, 0.f, 0.f, 0.f);
        for (int j0 = 0; j0 < deg; j0 += 32) {
            const int m = min(32, deg - j0);
            const int idx = (lane < m) ? g_csr_src[start + j0 + lane] : 0;
            int j = 0;
            for (; j + 1 < m; j += 2) {
                const int s0 = __shfl_sync(0xffffffffu, idx, j);
                const int s1 = __shfl_sync(0xffffffffu, idx, j + 1);
                const float4 v0 = ((const float4*)(x + (size_t)s0 * 128))[lane];
                const float4 v1 = ((const float4*)(x + (size_t)s1 * 128))[lane];
                a0.x += v0.x; a0.y += v0.y; a0.z += v0.z; a0.w += v0.w;
                a1.x += v1.x; a1.y += v1.y; a1.z += v1.z; a1.w += v1.w;
            }
            if (j < m) {
                const int s0 = __shfl_sync(0xffffffffu, idx, j);
                const float4 v0 = ((const float4*)(x + (size_t)s0 * 128))[lane];
                a0.x += v0.x; a0.y += v0.y; a0.z += v0.z; a0.w += v0.w;
            }
        }
        a0.x += a1.x; a0.y += a1.y; a0.z += a1.z; a0.w += a1.w;
        ((float4*)(g_mx + (size_t)n * 128))[lane] = a0;
    }
}

// ---------------- scores + global max ----------------
__global__ void scores_kernel(const float* __restrict__ x,
                              const float* __restrict__ Wo,
                              const float* __restrict__ bo) {
    const int lane = threadIdx.x & 31;
    const int w = threadIdx.x >> 5;
    const int nw = blockDim.x >> 5;
    const float4 wv = ((const float4*)Wo)[lane];
    const float b = *bo;
    float lmax = -3.402823466e38f;
    for (int n = blockIdx.x * nw + w; n < NN; n += gridDim.x * nw) {
        const float4 xv = ((const float4*)(x + (size_t)n * 128))[lane];
        float d = xv.x * wv.x + xv.y * wv.y + xv.z * wv.z + xv.w * wv.w;
        #pragma unroll
        for (int o = 16; o; o >>= 1) d += __shfl_down_sync(0xffffffffu, d, o);
        if (lane == 0) {
            const float sc = d + b;
            g_scores[n] = sc;
            if (sc > lmax) lmax = sc;
        }
    }
    __shared__ float sm[8];
    lmax = __shfl_sync(0xffffffffu, lmax, 0);
    if (lane == 0) sm[w] = lmax;
    __syncthreads();
    if (threadIdx.x == 0) {
        float m = sm[0];
        for (int i = 1; i < nw; i++) m = fmaxf(m, sm[i]);
        atomicMax(&g_maxbits, enc_ordered(m));
    }
}

// ---------------- sum of exp ----------------
__global__ void sum_kernel() {
    const float maxf = dec_ordered(g_maxbits);
    float s = 0.f;
    for (int n = blockIdx.x * blockDim.x + threadIdx.x; n < NN;
         n += gridDim.x * blockDim.x)
        s += expf(g_scores[n] - maxf);
    #pragma unroll
    for (int o = 16; o; o >>= 1) s += __shfl_down_sync(0xffffffffu, s, o);
    __shared__ float sm[8];
    const int lane = threadIdx.x & 31, w = threadIdx.x >> 5;
    if (lane == 0) sm[w] = s;
    __syncthreads();
    if (threadIdx.x == 0) {
        float t = 0.f;
        const int nw = blockDim.x >> 5;
        for (int i = 0; i < nw; i++) t += sm[i];
        atomicAdd(&g_sum, t);
    }
}

// ---------------- normalize ----------------
__global__ void finalize_kernel(float* __restrict__ out) {
    const float maxf = dec_ordered(g_maxbits);
    const float inv = 1.0f / g_sum;
    const int n = blockIdx.x * blockDim.x + threadIdx.x;
    if (n < NN) out[n] = expf(g_scores[n] - maxf) * inv;
}

// ---------------- launch ----------------
extern "C" void kernel_launch(void* const* d_in, const int* in_sizes, int n_in,
                              void* d_out, int out_size) {
    const float* NF = (const float*)d_in[0];
    const float* EF = (const float*)d_in[1];
    const float* Wn = (const float*)d_in[2];
    const float* bn = (const float*)d_in[3];
    const float* We = (const float*)d_in[4];
    const float* be = (const float*)d_in[5];
    const float* W1 = (const float*)d_in[6];
    const float* b1 = (const float*)d_in[7];
    const float* W2 = (const float*)d_in[8];
    const float* b2 = (const float*)d_in[9];
    const float* Wo = (const float*)d_in[10];
    const float* bo = (const float*)d_in[11];
    const void*  EI = d_in[12];
    float* out = (float*)d_out;

    float *px0, *px1, *pmx, *pme;
    cudaGetSymbolAddress((void**)&px0, g_x0);
    cudaGetSymbolAddress((void**)&px1, g_x1);
    cudaGetSymbolAddress((void**)&pmx, g_mx);
    cudaGetSymbolAddress((void**)&pme, g_me);

    const int SMEM_128 = (128 * 128 + 128 * XSTR) * 4;   // ~99 KB
    const int SMEM_256 = (256 * 128 + 256 * XSTR) * 4;   // ~198 KB
    cudaFuncSetAttribute(proj_kernel<128, false>,
                         cudaFuncAttributeMaxDynamicSharedMemorySize, SMEM_128);
    cudaFuncSetAttribute(proj_kernel<256, true>,
                         cudaFuncAttributeMaxDynamicSharedMemorySize, SMEM_256);

    const int nTilesN = (NN + 63) / 64;   // 782
    const int nTilesE = EE / 128;         // 6250

    // edge index normalization + cnt zeroing
    convert_edges<<<512, 256>>>(EI);
    // zero m_e + softmax scalars; precompute We B-fragments (bf16 hi/lo)
    zero_me<<<2048, 256>>>();
    wconv_kernel<<<4, 256>>>(We);
    // CSR build (topology computed once, reused by both conv layers)
    hist_kernel<<<512, 256>>>();
    scan_reduce<<<NB_SCAN, 256>>>();
    scan_partials<<<1, 256>>>();
    scan_final<<<NB_SCAN, 256>>>();
    fill_kernel<<<512, 256>>>();
    // x0 = relu(NF @ Wn + bn)
    proj_kernel<128, false><<<nTilesN, 256, SMEM_128>>>(NF, nullptr, Wn, bn, px0, NN);
    // m_e = segment_sum(relu(EF @ We + be), dst)  — mma.sync bf16x3, smem-free
    edge_proj_mma<<<nTilesE, 256>>>(EF, be);
    // layer 1
    gather_csr<<<1184, 256>>>(px0);
    proj_kernel<256, true><<<nTilesN, 256, SMEM_256>>>(pmx, pme, W1, b1, px1, NN);
    // layer 2
    gather_csr<<<1184, 256>>>(px1);
    proj_kernel<256, true><<<nTilesN, 256, SMEM_256>>>(pmx, pme, W2, b2, px0, NN);
    // scores + softmax
    scores_kernel<<<512, 128>>>(px0, Wo, bo);
    sum_kernel<<<512, 256>>>();
    finalize_kernel<<<(NN + 255) / 256, 256>>>(out);
}

// round 13
// speedup vs baseline: 1.6432x; 1.4514x over previous
#include <cuda_runtime.h>
#include <cuda_bf16.h>
#include <cstdint>
#include <cstddef>

#define NN 50000
#define EE 800000
#define HID 128
#define EDIM 32
#define NB_SCAN 196  // ceil(NN/256)

// ---------------- scratch (static __device__ — allocation-free) ----------------
__device__ __align__(16) float g_x0[(size_t)NN * HID];
__device__ __align__(16) float g_x1[(size_t)NN * HID];
__device__ __align__(16) float g_mx[(size_t)NN * HID];
__device__ __align__(16) float g_me[(size_t)NN * HID];
__device__ __align__(16) float g_scores[NN];
__device__ int g_src[EE];
__device__ int g_dst[EE];
__device__ int g_csr_src[EE];
__device__ int g_cnt[NN];
__device__ int g_rowptr[NN];
__device__ int g_cur[NN];
__device__ int g_partial[256];
__device__ unsigned g_maxbits;
__device__ float g_sum;
// edge B fragments (We^T): [ks(2)][nb(16)][lane(32)][2] u32 (hi / lo arrays)
__device__ __align__(16) uint32_t g_bfh[2 * 16 * 32 * 2];
__device__ __align__(16) uint32_t g_bfl[2 * 16 * 32 * 2];
// proj B fragments, interleaved uint4 = (b0h,b1h,b0l,b1l): [ks][nb(16)][lane]
__device__ __align__(16) uint4 g_bfn[8 * 16 * 32];    // Wn  (K=128)
__device__ __align__(16) uint4 g_bf1[16 * 16 * 32];   // W1  (K=256)
__device__ __align__(16) uint4 g_bf2[16 * 16 * 32];   // W2  (K=256)

// ---------------- helpers ----------------
__device__ __forceinline__ void red_add_v4(float* addr, float4 v) {
    asm volatile("red.global.add.v4.f32 [%0], {%1,%2,%3,%4};"
                 :: "l"(addr), "f"(v.x), "f"(v.y), "f"(v.z), "f"(v.w)
                 : "memory");
}
__device__ __forceinline__ unsigned enc_ordered(float f) {
    unsigned b = __float_as_uint(f);
    return (b & 0x80000000u) ? ~b : (b | 0x80000000u);
}
__device__ __forceinline__ float dec_ordered(unsigned u) {
    unsigned b = (u & 0x80000000u) ? (u ^ 0x80000000u) : ~u;
    return __uint_as_float(b);
}
// pack two fp32 -> bf16x2 (x low half, y high half), plus residuals
__device__ __forceinline__ uint32_t pack_bf16_hi(float x, float y) {
    uint32_t h;
    asm("cvt.rn.bf16x2.f32 %0, %1, %2;" : "=r"(h) : "f"(y), "f"(x));
    return h;
}
__device__ __forceinline__ uint32_t pack_bf16_lo(float x, float y, uint32_t h) {
    const float rx = x - __uint_as_float(h << 16);
    const float ry = y - __uint_as_float(h & 0xffff0000u);
    uint32_t l;
    asm("cvt.rn.bf16x2.f32 %0, %1, %2;" : "=r"(l) : "f"(ry), "f"(rx));
    return l;
}
// mma.sync m16n8k16 row.col f32.bf16.bf16.f32, C==D accumulate
__device__ __forceinline__ void mma_bf16(float& d0, float& d1, float& d2, float& d3,
                                         uint32_t a0, uint32_t a1, uint32_t a2,
                                         uint32_t a3, uint32_t b0, uint32_t b1) {
    asm volatile(
        "mma.sync.aligned.m16n8k16.row.col.f32.bf16.bf16.f32 "
        "{%0,%1,%2,%3}, {%4,%5,%6,%7}, {%8,%9}, {%0,%1,%2,%3};"
        : "+f"(d0), "+f"(d1), "+f"(d2), "+f"(d3)
        : "r"(a0), "r"(a1), "r"(a2), "r"(a3), "r"(b0), "r"(b1));
}

// ---------------- edge index normalization + fused dst histogram ----------------
// g_cnt must be zeroed BEFORE this kernel (done in zero_me, launched first).
__global__ void convert_edges(const void* __restrict__ ei) {
    __shared__ int is64;
    if (threadIdx.x == 0) {
        const int* p = (const int*)ei;
        int z = 0;
        #pragma unroll
        for (int i = 0; i < 64; i++) z |= p[2 * i + 1];
        is64 = (z == 0);
    }
    __syncthreads();
    const int idx = blockIdx.x * blockDim.x + threadIdx.x;
    const int stride = gridDim.x * blockDim.x;
    if (is64) {
        const long long* p = (const long long*)ei;
        for (int e = idx; e < EE; e += stride) {
            const int d = (int)p[EE + e];
            g_src[e] = (int)p[e];
            g_dst[e] = d;
            atomicAdd(&g_cnt[d], 1);
        }
    } else {
        const int* p = (const int*)ei;
        for (int e = idx; e < EE; e += stride) {
            const int d = p[EE + e];
            g_src[e] = p[e];
            g_dst[e] = d;
            atomicAdd(&g_cnt[d], 1);
        }
    }
}

// ---------------- CSR scan + fill ----------------
__global__ void scan_reduce() {
    __shared__ int sh[256];
    const int t = threadIdx.x;
    const int i = blockIdx.x * 256 + t;
    sh[t] = (i < NN) ? g_cnt[i] : 0;
    __syncthreads();
    #pragma unroll
    for (int o = 128; o; o >>= 1) {
        if (t < o) sh[t] += sh[t + o];
        __syncthreads();
    }
    if (t == 0) g_partial[blockIdx.x] = sh[0];
}

__global__ void scan_partials() {
    __shared__ int sh[256];
    const int t = threadIdx.x;
    const int v = (t < NB_SCAN) ? g_partial[t] : 0;
    sh[t] = v;
    __syncthreads();
    #pragma unroll
    for (int off = 1; off < 256; off <<= 1) {
        int a = (t >= off) ? sh[t - off] : 0;
        __syncthreads();
        sh[t] += a;
        __syncthreads();
    }
    g_partial[t] = sh[t] - v;   // exclusive
}

__global__ void scan_final() {
    __shared__ int sh[256];
    const int t = threadIdx.x;
    const int i = blockIdx.x * 256 + t;
    const int v = (i < NN) ? g_cnt[i] : 0;
    sh[t] = v;
    __syncthreads();
    #pragma unroll
    for (int off = 1; off < 256; off <<= 1) {
        int a = (t >= off) ? sh[t - off] : 0;
        __syncthreads();
        sh[t] += a;
        __syncthreads();
    }
    if (i < NN) {
        const int excl = sh[t] - v + g_partial[blockIdx.x];
        g_rowptr[i] = excl;
        g_cur[i] = excl;
    }
}

__global__ void fill_kernel() {
    const int idx = blockIdx.x * blockDim.x + threadIdx.x;
    const int stride = gridDim.x * blockDim.x;
    for (int e = idx; e < EE; e += stride) {
        const int d = g_dst[e];
        const int p = atomicAdd(&g_cur[d], 1);
        g_csr_src[p] = g_src[e];
    }
}

// ---------------- zero m_e + cnt + scalars (runs FIRST) ----------------
__global__ void zero_me() {
    const int n4 = NN * HID / 4;
    float4* a = (float4*)g_me;
    const float4 z = make_float4(0.f, 0.f, 0.f, 0.f);
    const int idx = blockIdx.x * blockDim.x + threadIdx.x;
    const int stride = gridDim.x * blockDim.x;
    for (int i = idx; i < n4; i += stride) a[i] = z;
    for (int i = idx; i < NN; i += stride) g_cnt[i] = 0;
    if (blockIdx.x == 0 && threadIdx.x == 0) { g_maxbits = 0u; g_sum = 0.f; }
}

// ---------------- edge B-fragment precompute (We^T, hi/lo arrays) ----------------
__global__ void wconv_kernel(const float* __restrict__ We) {
    const int t = blockIdx.x * blockDim.x + threadIdx.x;
    if (t >= 1024) return;
    const int lane = t & 31;
    const int nb = (t >> 5) & 15;
    const int ks = t >> 9;
    const int n = nb * 8 + (lane >> 2);
    const int k0 = ks * 16 + (lane & 3) * 2;
    const float w00 = We[(k0 + 0) * 128 + n];
    const float w01 = We[(k0 + 1) * 128 + n];
    const float w10 = We[(k0 + 8) * 128 + n];
    const float w11 = We[(k0 + 9) * 128 + n];
    const uint32_t b0h = pack_bf16_hi(w00, w01);
    const uint32_t b1h = pack_bf16_hi(w10, w11);
    const uint32_t b0l = pack_bf16_lo(w00, w01, b0h);
    const uint32_t b1l = pack_bf16_lo(w10, w11, b1h);
    const int idx = ((ks * 16 + nb) * 32 + lane) * 2;
    g_bfh[idx] = b0h; g_bfh[idx + 1] = b1h;
    g_bfl[idx] = b0l; g_bfl[idx + 1] = b1l;
}

// ---------------- proj B-fragment precompute (interleaved uint4) ----------------
// out[(ks*16+nb)*32+lane] = (b0h, b1h, b0l, b1l) for W (K x 128), K = KS*16.
__global__ void wconv2_kernel(const float* __restrict__ W, uint4* __restrict__ out,
                              int KS) {
    const int t = blockIdx.x * blockDim.x + threadIdx.x;
    if (t >= KS * 512) return;
    const int lane = t & 31;
    const int nb = (t >> 5) & 15;
    const int ks = t >> 9;
    const int n = nb * 8 + (lane >> 2);
    const int k0 = ks * 16 + (lane & 3) * 2;
    const float w00 = W[(k0 + 0) * 128 + n];
    const float w01 = W[(k0 + 1) * 128 + n];
    const float w10 = W[(k0 + 8) * 128 + n];
    const float w11 = W[(k0 + 9) * 128 + n];
    const uint32_t b0h = pack_bf16_hi(w00, w01);
    const uint32_t b1h = pack_bf16_hi(w10, w11);
    out[(ks * 16 + nb) * 32 + lane] =
        make_uint4(b0h, b1h, pack_bf16_lo(w00, w01, b0h), pack_bf16_lo(w10, w11, b1h));
}

// ---------------- mma.sync projection GEMM: out = relu(X @ W + b) ----------------
// Block = 256 thr = 8 warps. Tile = 128 rows x 128 cols.
// Warp: wr = w&3 -> rows [wr*32,+32) as 2 m16 row-blocks; wc = w>>2 -> cols
// [wc*64,+64) as 8 n-blocks. K = KS*16, bf16x3 (3 mma per (rb,nb,ks)).
// One uint4 B-load feeds 6 MMAs (2 row-blocks). X rows clamped; stores guarded.
template <int KS, bool CONCAT>
__global__ __launch_bounds__(256)
void proj_mma(const float* __restrict__ in0, const float* __restrict__ in1,
              const uint4* __restrict__ Bf, const float* __restrict__ bias,
              float* __restrict__ out, int rows) {
    const int tid = threadIdx.x;
    const int lane = tid & 31;
    const int w = tid >> 5;
    const int wr = w & 3;
    const int wc = w >> 2;
    const int tile0 = blockIdx.x * 128;
    const int g = lane >> 2;
    const int c0 = (lane & 3) * 2;
    const int rbase = tile0 + wr * 32 + g;

    // clamped row pointers (both sources have row stride 128)
    const float* pA0[2][2];
    const float* pA1[2][2];
    #pragma unroll
    for (int rb = 0; rb < 2; rb++) {
        #pragma unroll
        for (int rh = 0; rh < 2; rh++) {
            const int r = min(rbase + rb * 16 + rh * 8, rows - 1);
            pA0[rb][rh] = in0 + (size_t)r * 128;
            if (CONCAT) pA1[rb][rh] = in1 + (size_t)r * 128;
        }
    }

    // accumulators init with bias
    float d[2][8][4];
    #pragma unroll
    for (int nb = 0; nb < 8; nb++) {
        const float2 bb = *(const float2*)(bias + wc * 64 + nb * 8 + c0);
        #pragma unroll
        for (int rb = 0; rb < 2; rb++) {
            d[rb][nb][0] = bb.x; d[rb][nb][1] = bb.y;
            d[rb][nb][2] = bb.x; d[rb][nb][3] = bb.y;
        }
    }

    #pragma unroll
    for (int ks = 0; ks < KS; ks++) {
        uint32_t ah[2][4], al[2][4];
        #pragma unroll
        for (int rb = 0; rb < 2; rb++) {
            #pragma unroll
            for (int half = 0; half < 2; half++) {
                const int k = ks * 16 + half * 8 + c0;
                const int kk = k & 127;
                const float* q0 = (CONCAT && k >= 128) ? pA1[rb][0] : pA0[rb][0];
                const float* q1 = (CONCAT && k >= 128) ? pA1[rb][1] : pA0[rb][1];
                const float2 f0 = *(const float2*)(q0 + kk);
                const float2 f1 = *(const float2*)(q1 + kk);
                const uint32_t h0 = pack_bf16_hi(f0.x, f0.y);
                const uint32_t h1 = pack_bf16_hi(f1.x, f1.y);
                ah[rb][half * 2 + 0] = h0;
                ah[rb][half * 2 + 1] = h1;
                al[rb][half * 2 + 0] = pack_bf16_lo(f0.x, f0.y, h0);
                al[rb][half * 2 + 1] = pack_bf16_lo(f1.x, f1.y, h1);
            }
        }
        #pragma unroll
        for (int nb = 0; nb < 8; nb++) {
            const uint4 B = Bf[(ks * 16 + wc * 8 + nb) * 32 + lane];
            #pragma unroll
            for (int rb = 0; rb < 2; rb++) {
                mma_bf16(d[rb][nb][0], d[rb][nb][1], d[rb][nb][2], d[rb][nb][3],
                         ah[rb][0], ah[rb][1], ah[rb][2], ah[rb][3], B.x, B.y);
                mma_bf16(d[rb][nb][0], d[rb][nb][1], d[rb][nb][2], d[rb][nb][3],
                         ah[rb][0], ah[rb][1], ah[rb][2], ah[rb][3], B.z, B.w);
                mma_bf16(d[rb][nb][0], d[rb][nb][1], d[rb][nb][2], d[rb][nb][3],
                         al[rb][0], al[rb][1], al[rb][2], al[rb][3], B.x, B.y);
            }
        }
    }

    // epilogue: shfl_xor(1) assembles float4; guarded STG.128
    const int colbase = wc * 64 + (lane & 2) * 2;
    #pragma unroll
    for (int rb = 0; rb < 2; rb++) {
        const int myrow = rbase + rb * 16 + ((lane & 1) ? 8 : 0);
        float* op = out + (size_t)myrow * 128 + colbase;
        #pragma unroll
        for (int nb = 0; nb < 8; nb++) {
            const float p0 = __shfl_xor_sync(0xffffffffu, d[rb][nb][0], 1);
            const float p1 = __shfl_xor_sync(0xffffffffu, d[rb][nb][1], 1);
            const float p2 = __shfl_xor_sync(0xffffffffu, d[rb][nb][2], 1);
            const float p3 = __shfl_xor_sync(0xffffffffu, d[rb][nb][3], 1);
            float4 v;
            if ((lane & 1) == 0) {
                v = make_float4(d[rb][nb][0], d[rb][nb][1], p0, p1);
            } else {
                v = make_float4(p2, p3, d[rb][nb][2], d[rb][nb][3]);
            }
            v.x = fmaxf(v.x, 0.f); v.y = fmaxf(v.y, 0.f);
            v.z = fmaxf(v.z, 0.f); v.w = fmaxf(v.w, 0.f);
            if (myrow < rows) *(float4*)(op + nb * 8) = v;
        }
    }
}

// ---------------- mma.sync edge projection + segment-sum into m_e (R12) ---------
__global__ __launch_bounds__(256)
void edge_proj_mma(const float* __restrict__ EF,
                   const float* __restrict__ be) {
    const int tid = threadIdx.x;
    const int lane = tid & 31;
    const int w = tid >> 5;
    const int tile0 = blockIdx.x * 128;

    const int g = lane >> 2;
    const int c0 = (lane & 3) * 2;

    const int myrow = w * 16 + g + ((lane & 1) ? 8 : 0);
    const int dst = __ldg(&g_dst[tile0 + myrow]);
    float* outp = g_me + (size_t)dst * 128 + (lane & 2) * 2;

    const float* rowp0 = EF + (size_t)(tile0 + w * 16 + g) * EDIM;
    const float* rowp1 = rowp0 + 8 * EDIM;
    uint32_t ah[2][4], al[2][4];
    #pragma unroll
    for (int ks = 0; ks < 2; ks++) {
        #pragma unroll
        for (int half = 0; half < 2; half++) {
            const int k = ks * 16 + half * 8 + c0;
            const float2 f0 = *(const float2*)(rowp0 + k);
            const float2 f1 = *(const float2*)(rowp1 + k);
            const uint32_t h0 = pack_bf16_hi(f0.x, f0.y);
            const uint32_t h1 = pack_bf16_hi(f1.x, f1.y);
            ah[ks][half * 2 + 0] = h0;
            ah[ks][half * 2 + 1] = h1;
            al[ks][half * 2 + 0] = pack_bf16_lo(f0.x, f0.y, h0);
            al[ks][half * 2 + 1] = pack_bf16_lo(f1.x, f1.y, h1);
        }
    }

    const uint32_t* bh = g_bfh;
    const uint32_t* bl = g_bfl;
    #pragma unroll
    for (int nb = 0; nb < 16; nb++) {
        const float2 bb = *(const float2*)(be + nb * 8 + c0);
        float d0 = bb.x, d1 = bb.y, d2 = bb.x, d3 = bb.y;
        #pragma unroll
        for (int ks = 0; ks < 2; ks++) {
            const int bi = ((ks * 16 + nb) * 32 + lane) * 2;
            const uint32_t bh0 = bh[bi], bh1 = bh[bi + 1];
            const uint32_t bl0 = bl[bi], bl1 = bl[bi + 1];
            mma_bf16(d0, d1, d2, d3,
                     ah[ks][0], ah[ks][1], ah[ks][2], ah[ks][3], bh0, bh1);
            mma_bf16(d0, d1, d2, d3,
                     ah[ks][0], ah[ks][1], ah[ks][2], ah[ks][3], bl0, bl1);
            mma_bf16(d0, d1, d2, d3,
                     al[ks][0], al[ks][1], al[ks][2], al[ks][3], bh0, bh1);
        }
        const float p0 = __shfl_xor_sync(0xffffffffu, d0, 1);
        const float p1 = __shfl_xor_sync(0xffffffffu, d1, 1);
        const float p2 = __shfl_xor_sync(0xffffffffu, d2, 1);
        const float p3 = __shfl_xor_sync(0xffffffffu, d3, 1);
        float4 v;
        if ((lane & 1) == 0) {
            v = make_float4(d0, d1, p0, p1);
        } else {
            v = make_float4(p2, p3, d2, d3);
        }
        v.x = fmaxf(v.x, 0.f); v.y = fmaxf(v.y, 0.f);
        v.z = fmaxf(v.z, 0.f); v.w = fmaxf(v.w, 0.f);
        red_add_v4(outp + nb * 8, v);
    }
}

// ---------------- CSR aggregation (R8, unchanged) ----------------
__global__ void gather_csr(const float* __restrict__ x) {
    const int lane = threadIdx.x & 31;
    const int warp = (blockIdx.x * blockDim.x + threadIdx.x) >> 5;
    const int nwarps = (gridDim.x * blockDim.x) >> 5;
    for (int n = warp; n < NN; n += nwarps) {
        const int start = g_rowptr[n];
        const int deg = g_cnt[n];
        float4 a0 = make_float4(0.f, 0.f, 0.f, 0.f);
        float4 a1 = make_float4(0.f, 0.f, 0.f, 0.f);
        for (int j0 = 0; j0 < deg; j0 += 32) {
            const int m = min(32, deg - j0);
            const int idx = (lane < m) ? g_csr_src[start + j0 + lane] : 0;
            int j = 0;
            for (; j + 1 < m; j += 2) {
                const int s0 = __shfl_sync(0xffffffffu, idx, j);
                const int s1 = __shfl_sync(0xffffffffu, idx, j + 1);
                const float4 v0 = ((const float4*)(x + (size_t)s0 * 128))[lane];
                const float4 v1 = ((const float4*)(x + (size_t)s1 * 128))[lane];
                a0.x += v0.x; a0.y += v0.y; a0.z += v0.z; a0.w += v0.w;
                a1.x += v1.x; a1.y += v1.y; a1.z += v1.z; a1.w += v1.w;
            }
            if (j < m) {
                const int s0 = __shfl_sync(0xffffffffu, idx, j);
                const float4 v0 = ((const float4*)(x + (size_t)s0 * 128))[lane];
                a0.x += v0.x; a0.y += v0.y; a0.z += v0.z; a0.w += v0.w;
            }
        }
        a0.x += a1.x; a0.y += a1.y; a0.z += a1.z; a0.w += a1.w;
        ((float4*)(g_mx + (size_t)n * 128))[lane] = a0;
    }
}

// ---------------- scores + global max ----------------
__global__ void scores_kernel(const float* __restrict__ x,
                              const float* __restrict__ Wo,
                              const float* __restrict__ bo) {
    const int lane = threadIdx.x & 31;
    const int w = threadIdx.x >> 5;
    const int nw = blockDim.x >> 5;
    const float4 wv = ((const float4*)Wo)[lane];
    const float b = *bo;
    float lmax = -3.402823466e38f;
    for (int n = blockIdx.x * nw + w; n < NN; n += gridDim.x * nw) {
        const float4 xv = ((const float4*)(x + (size_t)n * 128))[lane];
        float d = xv.x * wv.x + xv.y * wv.y + xv.z * wv.z + xv.w * wv.w;
        #pragma unroll
        for (int o = 16; o; o >>= 1) d += __shfl_down_sync(0xffffffffu, d, o);
        if (lane == 0) {
            const float sc = d + b;
            g_scores[n] = sc;
            if (sc > lmax) lmax = sc;
        }
    }
    __shared__ float sm[8];
    lmax = __shfl_sync(0xffffffffu, lmax, 0);
    if (lane == 0) sm[w] = lmax;
    __syncthreads();
    if (threadIdx.x == 0) {
        float m = sm[0];
        for (int i = 1; i < nw; i++) m = fmaxf(m, sm[i]);
        atomicMax(&g_maxbits, enc_ordered(m));
    }
}

// ---------------- sum of exp ----------------
__global__ void sum_kernel() {
    const float maxf = dec_ordered(g_maxbits);
    float s = 0.f;
    for (int n = blockIdx.x * blockDim.x + threadIdx.x; n < NN;
         n += gridDim.x * blockDim.x)
        s += expf(g_scores[n] - maxf);
    #pragma unroll
    for (int o = 16; o; o >>= 1) s += __shfl_down_sync(0xffffffffu, s, o);
    __shared__ float sm[8];
    const int lane = threadIdx.x & 31, w = threadIdx.x >> 5;
    if (lane == 0) sm[w] = s;
    __syncthreads();
    if (threadIdx.x == 0) {
        float t = 0.f;
        const int nw = blockDim.x >> 5;
        for (int i = 0; i < nw; i++) t += sm[i];
        atomicAdd(&g_sum, t);
    }
}

// ---------------- normalize ----------------
__global__ void finalize_kernel(float* __restrict__ out) {
    const float maxf = dec_ordered(g_maxbits);
    const float inv = 1.0f / g_sum;
    const int n = blockIdx.x * blockDim.x + threadIdx.x;
    if (n < NN) out[n] = expf(g_scores[n] - maxf) * inv;
}

// ---------------- launch ----------------
extern "C" void kernel_launch(void* const* d_in, const int* in_sizes, int n_in,
                              void* d_out, int out_size) {
    const float* NF = (const float*)d_in[0];
    const float* EF = (const float*)d_in[1];
    const float* Wn = (const float*)d_in[2];
    const float* bn = (const float*)d_in[3];
    const float* We = (const float*)d_in[4];
    const float* be = (const float*)d_in[5];
    const float* W1 = (const float*)d_in[6];
    const float* b1 = (const float*)d_in[7];
    const float* W2 = (const float*)d_in[8];
    const float* b2 = (const float*)d_in[9];
    const float* Wo = (const float*)d_in[10];
    const float* bo = (const float*)d_in[11];
    const void*  EI = d_in[12];
    float* out = (float*)d_out;

    float *px0, *px1, *pmx, *pme;
    uint4 *pbfn, *pbf1, *pbf2;
    cudaGetSymbolAddress((void**)&px0, g_x0);
    cudaGetSymbolAddress((void**)&px1, g_x1);
    cudaGetSymbolAddress((void**)&pmx, g_mx);
    cudaGetSymbolAddress((void**)&pme, g_me);
    cudaGetSymbolAddress((void**)&pbfn, g_bfn);
    cudaGetSymbolAddress((void**)&pbf1, g_bf1);
    cudaGetSymbolAddress((void**)&pbf2, g_bf2);

    const int nTilesN = (NN + 127) / 128;   // 391
    const int nTilesE = EE / 128;           // 6250

    // zero m_e + cnt + scalars (must precede fused hist in convert_edges)
    zero_me<<<2048, 256>>>();
    // edge index normalization + fused dst histogram
    convert_edges<<<512, 256>>>(EI);
    // weight B-fragment precompute
    wconv_kernel<<<4, 256>>>(We);
    wconv2_kernel<<<16, 256>>>(Wn, pbfn, 8);
    wconv2_kernel<<<32, 256>>>(W1, pbf1, 16);
    wconv2_kernel<<<32, 256>>>(W2, pbf2, 16);
    // CSR scan + fill
    scan_reduce<<<NB_SCAN, 256>>>();
    scan_partials<<<1, 256>>>();
    scan_final<<<NB_SCAN, 256>>>();
    fill_kernel<<<512, 256>>>();
    // x0 = relu(NF @ Wn + bn)  — mma.sync bf16x3
    proj_mma<8, false><<<nTilesN, 256>>>(NF, nullptr, pbfn, bn, px0, NN);
    // m_e = segment_sum(relu(EF @ We + be), dst)  — mma.sync bf16x3
    edge_proj_mma<<<nTilesE, 256>>>(EF, be);
    // layer 1
    gather_csr<<<1184, 256>>>(px0);
    proj_mma<16, true><<<nTilesN, 256>>>(pmx, pme, pbf1, b1, px1, NN);
    // layer 2
    gather_csr<<<1184, 256>>>(px1);
    proj_mma<16, true><<<nTilesN, 256>>>(pmx, pme, pbf2, b2, px0, NN);
    // scores + softmax
    scores_kernel<<<512, 128>>>(px0, Wo, bo);
    sum_kernel<<<512, 256>>>();
    finalize_kernel<<<(NN + 255) / 256, 256>>>(out);
}